// round 3
// baseline (speedup 1.0000x reference)
#include <cuda_runtime.h>
#include <math.h>

#define BB 512
#define TT 64
#define NINx 63
#define HH 128

// ------------------------- device scratch (static) -------------------------
__device__ float g_attn[BB * 64];
__device__ float g_gin[(size_t)BB * TT * 512];   // permuted gate order, biases folded
__device__ float g_enc[(size_t)BB * TT * HH];    // input_encoded
__device__ float g_eproj[(size_t)BB * TT * HH];  // enc_proj (+dec_b1)
__device__ float g_WhhT[2][128 * 512];           // [dec][k][gate'] transposed+permuted
__device__ float g_dWihP[512], g_dbP[512];       // permuted dec input weights/biases
__device__ float g_hA[BB * HH], g_hB[BB * HH], g_c[BB * HH];
__device__ float g_dhA[BB * HH], g_dhB[BB * HH], g_dc[BB * HH];
__device__ float g_u[BB * HH];
__device__ float g_ctx[BB * HH];
__device__ float g_yt[BB];

__device__ __forceinline__ float tanh_fast(float v) {
    float r; asm("tanh.approx.f32 %0, %1;" : "=f"(r) : "f"(v)); return r;
}
__device__ __forceinline__ float sig_fast(float v) {
    return 0.5f * tanh_fast(0.5f * v) + 0.5f;
}

// ------------------------- init states -------------------------
__global__ void zero_state() {
    int i = blockIdx.x * blockDim.x + threadIdx.x;  // 65536 = BB*HH
    g_hA[i] = 0.f; g_c[i] = 0.f; g_dhA[i] = 0.f; g_dc[i] = 0.f;
}

// ------------------------- permute/transpose recurrent weights -------------------------
__global__ void prep_weights(const float* __restrict__ eWhh,
                             const float* __restrict__ dWhh,
                             const float* __restrict__ dWih,
                             const float* __restrict__ dbih,
                             const float* __restrict__ dbhh) {
    int i = blockIdx.x * blockDim.x + threadIdx.x;  // 65536 = 512*128
    int gp = i & 511, k = i >> 9;
    int orig = (gp & 3) * HH + (gp >> 2);
    g_WhhT[0][k * 512 + gp] = eWhh[orig * HH + k];
    g_WhhT[1][k * 512 + gp] = dWhh[orig * HH + k];
    if (k == 0) {
        g_dWihP[gp] = dWih[orig];
        g_dbP[gp] = dbih[orig] + dbhh[orig];
    }
}

// ------------------------- encoder attention (time-invariant) -------------------------
__global__ void prep_attn(const float* __restrict__ x,
                          const float* __restrict__ attnW,
                          const float* __restrict__ attnB) {
    __shared__ float s_s[64];
    __shared__ float red[2];
    int b = blockIdx.x, n = threadIdx.x;
    float s = -1e30f;
    if (n < NINx) {
        float acc = attnB[0];
        const float* wt = attnW + 2 * HH;
        #pragma unroll 8
        for (int t = 0; t < TT; t++) acc = fmaf(x[b * 4096 + t * 64 + n + 1], wt[t], acc);
        s = acc;
    }
    s_s[n] = s;
    __syncthreads();
    if (n < 32) {
        float m = fmaxf(s_s[n], s_s[n + 32]);
        #pragma unroll
        for (int o = 16; o; o >>= 1) m = fmaxf(m, __shfl_xor_sync(0xffffffffu, m, o));
        if (n == 0) red[0] = m;
    }
    __syncthreads();
    float e = (n < NINx) ? expf(s - red[0]) : 0.f;
    s_s[n] = e;
    __syncthreads();
    if (n < 32) {
        float sm = s_s[n] + s_s[n + 32];
        #pragma unroll
        for (int o = 16; o; o >>= 1) sm += __shfl_xor_sync(0xffffffffu, sm, o);
        if (n == 0) red[1] = sm;
    }
    __syncthreads();
    if (n < 64) g_attn[b * 64 + n] = (n < NINx) ? e / red[1] : 0.f;
}

// ------------- gin[b,t,g'] = sum_n attn[b,n]*x[b,t,n+1]*Wih[orig(g'),n] + bias -------------
__global__ __launch_bounds__(256) void gin_gemm(const float* __restrict__ x,
                                                const float* __restrict__ Wih,
                                                const float* __restrict__ bih,
                                                const float* __restrict__ bhh) {
    __shared__ float attn_s[64];
    __shared__ float As[64][68];
    __shared__ float Ws[64][68];
    int bb = blockIdx.x;
    int g0 = blockIdx.y * 64;
    int tid = threadIdx.x;
    if (tid < 64) attn_s[tid] = g_attn[bb * 64 + tid];
    __syncthreads();
    #pragma unroll
    for (int i = 0; i < 16; i++) {
        int idx = tid + i * 256;
        int m = idx >> 6, k = idx & 63;
        As[k][m] = (k < NINx) ? attn_s[k] * x[bb * 4096 + m * 64 + k + 1] : 0.f;
        int gp = g0 + m;
        int orig = (gp & 3) * HH + (gp >> 2);
        Ws[k][m] = (k < NINx) ? Wih[orig * NINx + k] : 0.f;
    }
    __syncthreads();
    int tx = tid & 15, ty = tid >> 4;
    float acc[4][4];
    #pragma unroll
    for (int i = 0; i < 4; i++)
        #pragma unroll
        for (int j = 0; j < 4; j++) acc[i][j] = 0.f;
    #pragma unroll 4
    for (int k = 0; k < 64; k++) {
        float4 a = *reinterpret_cast<const float4*>(&As[k][ty * 4]);
        float4 w = *reinterpret_cast<const float4*>(&Ws[k][tx * 4]);
        float av[4] = {a.x, a.y, a.z, a.w};
        float wv[4] = {w.x, w.y, w.z, w.w};
        #pragma unroll
        for (int i = 0; i < 4; i++)
            #pragma unroll
            for (int j = 0; j < 4; j++) acc[i][j] = fmaf(av[i], wv[j], acc[i][j]);
    }
    #pragma unroll
    for (int i = 0; i < 4; i++) {
        int t = ty * 4 + i;
        #pragma unroll
        for (int j = 0; j < 4; j++) {
            int gp = g0 + tx * 4 + j;
            int orig = (gp & 3) * HH + (gp >> 2);
            g_gin[((size_t)bb * TT + t) * 512 + gp] = acc[i][j] + bih[orig] + bhh[orig];
        }
    }
}

// ------------------------- fused LSTM step (enc & dec) -------------------------
// grid (32 batch-tiles of 16, 8 gate-tiles of 64), 128 threads
__global__ __launch_bounds__(128) void lstm_step(int t, int dec) {
    __shared__ float As[128][18];  // h transposed: [k][batch]
    __shared__ float Ws[128][68];  // WhhT tile: [k][gate-in-tile]
    const float* h_in; float* h_out; float* c;
    if (dec) { h_in = (t & 1) ? g_dhB : g_dhA; h_out = (t & 1) ? g_dhA : g_dhB; c = g_dc; }
    else     { h_in = (t & 1) ? g_hB  : g_hA;  h_out = (t & 1) ? g_hA  : g_hB;  c = g_c;  }
    const float* WhhT = g_WhhT[dec];
    int b0 = blockIdx.x * 16;
    int g0 = blockIdx.y * 64;
    int tid = threadIdx.x;
    int tx = tid & 15, pr = tid >> 4;   // unit-in-tile, batch-pair
    int unit = (g0 >> 2) + tx;
    int bA = b0 + 2 * pr, bB = bA + 1;

    // --- prefetch per-output inputs (hide DRAM latency behind GEMM) ---
    float4 pre0, pre1;
    if (!dec) {
        pre0 = *reinterpret_cast<const float4*>(&g_gin[((size_t)bA * TT + t) * 512 + g0 + tx * 4]);
        pre1 = *reinterpret_cast<const float4*>(&g_gin[((size_t)bB * TT + t) * 512 + g0 + tx * 4]);
    } else {
        float4 wv = *reinterpret_cast<const float4*>(&g_dWihP[g0 + tx * 4]);
        float4 bv = *reinterpret_cast<const float4*>(&g_dbP[g0 + tx * 4]);
        float y0 = g_yt[bA], y1 = g_yt[bB];
        pre0 = make_float4(fmaf(y0, wv.x, bv.x), fmaf(y0, wv.y, bv.y),
                           fmaf(y0, wv.z, bv.z), fmaf(y0, wv.w, bv.w));
        pre1 = make_float4(fmaf(y1, wv.x, bv.x), fmaf(y1, wv.y, bv.y),
                           fmaf(y1, wv.z, bv.z), fmaf(y1, wv.w, bv.w));
    }
    float c0 = c[bA * HH + unit], c1 = c[bB * HH + unit];

    // --- stage h (transposed) ---
    {
        int b = tid & 15, k0 = (tid >> 4) * 16;
        const float4* hp = reinterpret_cast<const float4*>(h_in + (b0 + b) * HH + k0);
        #pragma unroll
        for (int i = 0; i < 4; i++) {
            float4 v = hp[i];
            As[k0 + 4 * i + 0][b] = v.x;
            As[k0 + 4 * i + 1][b] = v.y;
            As[k0 + 4 * i + 2][b] = v.z;
            As[k0 + 4 * i + 3][b] = v.w;
        }
    }
    // --- stage Whh tile (staggered k to avoid STS conflicts) ---
    {
        int j = (tid >> 3) * 4;  // 0..60
        int kb = tid & 7;
        #pragma unroll
        for (int i = 0; i < 16; i++) {
            int k = kb + 8 * i;
            float4 v = *reinterpret_cast<const float4*>(&WhhT[k * 512 + g0 + j]);
            *reinterpret_cast<float4*>(&Ws[k][j]) = v;
        }
    }
    __syncthreads();

    float a00 = 0.f, a01 = 0.f, a02 = 0.f, a03 = 0.f;
    float a10 = 0.f, a11 = 0.f, a12 = 0.f, a13 = 0.f;
    #pragma unroll 8
    for (int k = 0; k < 128; k++) {
        float2 a = *reinterpret_cast<const float2*>(&As[k][pr * 2]);
        float4 w = *reinterpret_cast<const float4*>(&Ws[k][tx * 4]);
        a00 = fmaf(a.x, w.x, a00); a01 = fmaf(a.x, w.y, a01);
        a02 = fmaf(a.x, w.z, a02); a03 = fmaf(a.x, w.w, a03);
        a10 = fmaf(a.y, w.x, a10); a11 = fmaf(a.y, w.y, a11);
        a12 = fmaf(a.y, w.z, a12); a13 = fmaf(a.y, w.w, a13);
    }

    // --- epilogue (fast activations) ---
    {
        float gi = a00 + pre0.x, gf = a01 + pre0.y, gg = a02 + pre0.z, go = a03 + pre0.w;
        float cv = sig_fast(gf) * c0 + sig_fast(gi) * tanh_fast(gg);
        float hv = sig_fast(go) * tanh_fast(cv);
        c[bA * HH + unit] = cv;
        h_out[bA * HH + unit] = hv;
        if (!dec) g_enc[((size_t)bA * TT + t) * HH + unit] = hv;
    }
    {
        float gi = a10 + pre1.x, gf = a11 + pre1.y, gg = a12 + pre1.z, go = a13 + pre1.w;
        float cv = sig_fast(gf) * c1 + sig_fast(gi) * tanh_fast(gg);
        float hv = sig_fast(go) * tanh_fast(cv);
        c[bB * HH + unit] = cv;
        h_out[bB * HH + unit] = hv;
        if (!dec) g_enc[((size_t)bB * TT + t) * HH + unit] = hv;
    }
}

// ------------------ enc_proj = input_encoded @ W1e^T + dec_b1 ------------------
__global__ __launch_bounds__(256) void eproj_gemm(const float* __restrict__ W1,
                                                  const float* __restrict__ b1) {
    __shared__ float As[64][68];
    __shared__ float Ws[64][68];
    int m0 = blockIdx.x * 64;
    int n0 = blockIdx.y * 64;
    int tid = threadIdx.x;
    int tx = tid & 15, ty = tid >> 4;
    float acc[4][4];
    #pragma unroll
    for (int i = 0; i < 4; i++)
        #pragma unroll
        for (int j = 0; j < 4; j++) acc[i][j] = 0.f;
    for (int kc = 0; kc < 2; kc++) {
        __syncthreads();
        #pragma unroll
        for (int i = 0; i < 16; i++) {
            int idx = tid + i * 256;
            int m = idx >> 6, k = idx & 63;
            As[k][m] = g_enc[(size_t)(m0 + m) * HH + kc * 64 + k];
            Ws[k][m] = W1[(n0 + m) * 384 + 256 + kc * 64 + k];
        }
        __syncthreads();
        #pragma unroll 4
        for (int k = 0; k < 64; k++) {
            float4 a = *reinterpret_cast<const float4*>(&As[k][ty * 4]);
            float4 w = *reinterpret_cast<const float4*>(&Ws[k][tx * 4]);
            float av[4] = {a.x, a.y, a.z, a.w};
            float wv[4] = {w.x, w.y, w.z, w.w};
            #pragma unroll
            for (int i = 0; i < 4; i++)
                #pragma unroll
                for (int j = 0; j < 4; j++) acc[i][j] = fmaf(av[i], wv[j], acc[i][j]);
        }
    }
    #pragma unroll
    for (int i = 0; i < 4; i++) {
        int row = m0 + ty * 4 + i;
        #pragma unroll
        for (int j = 0; j < 4; j++) {
            int n = n0 + tx * 4 + j;
            g_eproj[(size_t)row * HH + n] = acc[i][j] + b1[n];
        }
    }
}

// ------------------ decoder: u = h @ W1h^T + c @ W1c^T ------------------
// grid (64 batch-tiles of 8, 2 e-tiles of 64), 128 threads
__global__ __launch_bounds__(128) void dec_proj(const float* __restrict__ W1, int t) {
    __shared__ float hcT[256][10];  // [k][batch], k<128 = h, k>=128 = c
    __shared__ float W1s[64][66];
    const float* h_in = (t & 1) ? g_dhB : g_dhA;
    int b0 = blockIdx.x * 8, e0 = blockIdx.y * 64, tid = threadIdx.x;
    // stage h,c transposed
    {
        int b = tid & 7, kq = tid >> 3;  // kq 0..15
        int k0 = kq * 16;
        const float* src = (k0 < 128) ? (h_in + (b0 + b) * HH + k0)
                                      : (g_dc + (b0 + b) * HH + (k0 - 128));
        const float4* sp = reinterpret_cast<const float4*>(src);
        #pragma unroll
        for (int i = 0; i < 4; i++) {
            float4 v = sp[i];
            hcT[k0 + 4 * i + 0][b] = v.x;
            hcT[k0 + 4 * i + 1][b] = v.y;
            hcT[k0 + 4 * i + 2][b] = v.z;
            hcT[k0 + 4 * i + 3][b] = v.w;
        }
    }
    int tx = tid & 31, pr = tid >> 5;  // e-pair, batch-pair
    float acc[2][2];
    acc[0][0] = acc[0][1] = acc[1][0] = acc[1][1] = 0.f;
    for (int kc = 0; kc < 4; kc++) {
        __syncthreads();
        {
            int e = tid & 15, kq = tid >> 4;  // kq 0..7
            int k0 = kq * 8;
            #pragma unroll
            for (int q = 0; q < 2; q++) {
                float4 v = *reinterpret_cast<const float4*>(
                    &W1[(e0 + e * 4 + q * 0) * 384]);  // placeholder avoided below
                (void)v;
            }
            // transpose-load W1 chunk: W1s[k][e] for e in tile, k in chunk
            #pragma unroll
            for (int i = 0; i < 8; i++) {
                int k = k0 + i;
                // each thread covers 4 e-columns: e*4..e*4+3
                float4 w;
                w.x = W1[(e0 + e * 4 + 0) * 384 + kc * 64 + k];
                w.y = W1[(e0 + e * 4 + 1) * 384 + kc * 64 + k];
                w.z = W1[(e0 + e * 4 + 2) * 384 + kc * 64 + k];
                w.w = W1[(e0 + e * 4 + 3) * 384 + kc * 64 + k];
                W1s[k][e * 4 + 0] = w.x;
                W1s[k][e * 4 + 1] = w.y;
                W1s[k][e * 4 + 2] = w.z;
                W1s[k][e * 4 + 3] = w.w;
            }
        }
        __syncthreads();
        #pragma unroll 8
        for (int k = 0; k < 64; k++) {
            float2 a = *reinterpret_cast<const float2*>(&hcT[kc * 64 + k][pr * 2]);
            float2 w = *reinterpret_cast<const float2*>(&W1s[k][tx * 2]);
            acc[0][0] = fmaf(a.x, w.x, acc[0][0]);
            acc[0][1] = fmaf(a.x, w.y, acc[0][1]);
            acc[1][0] = fmaf(a.y, w.x, acc[1][0]);
            acc[1][1] = fmaf(a.y, w.y, acc[1][1]);
        }
    }
    #pragma unroll
    for (int r = 0; r < 2; r++) {
        int b = b0 + pr * 2 + r;
        g_u[b * HH + e0 + tx * 2]     = acc[r][0];
        g_u[b * HH + e0 + tx * 2 + 1] = acc[r][1];
    }
}

// ---------- decoder attention + context + y_tilde (fused, per-batch block) ----------
__global__ __launch_bounds__(256) void dec_attn(const float* __restrict__ W2,
                                                const float* __restrict__ fcW,
                                                const float* __restrict__ fcb,
                                                const float* __restrict__ x, int t) {
    __shared__ float u_s[128];
    __shared__ float sc[64];
    __shared__ float red[8];
    int b = blockIdx.x, tid = threadIdx.x, lane = tid & 31, w = tid >> 5;
    if (tid < 128) u_s[tid] = g_u[b * HH + tid];
    __syncthreads();
    const float* ep = g_eproj + (size_t)b * TT * HH;
    #pragma unroll
    for (int i = 0; i < 8; i++) {
        int tt = w * 8 + i;
        float p = 0.f;
        #pragma unroll
        for (int q = 0; q < 4; q++) {
            int e = lane + q * 32;
            p = fmaf(W2[e], tanh_fast(ep[tt * HH + e] + u_s[e]), p);
        }
        #pragma unroll
        for (int o = 16; o; o >>= 1) p += __shfl_xor_sync(0xffffffffu, p, o);
        if (lane == 0) sc[tt] = p;
    }
    __syncthreads();
    if (w == 0) {
        float s0 = sc[lane], s1 = sc[lane + 32];
        float m = fmaxf(s0, s1);
        #pragma unroll
        for (int o = 16; o; o >>= 1) m = fmaxf(m, __shfl_xor_sync(0xffffffffu, m, o));
        float e0 = __expf(s0 - m), e1 = __expf(s1 - m);
        float sm = e0 + e1;
        #pragma unroll
        for (int o = 16; o; o >>= 1) sm += __shfl_xor_sync(0xffffffffu, sm, o);
        sc[lane] = e0 / sm;
        sc[lane + 32] = e1 / sm;
    }
    __syncthreads();
    float yp = 0.f;
    if (tid < 128) {
        const float* en = g_enc + (size_t)b * TT * HH;
        float a = 0.f;
        #pragma unroll 8
        for (int tt = 0; tt < 64; tt++) a = fmaf(sc[tt], en[tt * HH + tid], a);
        g_ctx[b * HH + tid] = a;
        yp = a * fcW[tid];
    }
    #pragma unroll
    for (int o = 16; o; o >>= 1) yp += __shfl_xor_sync(0xffffffffu, yp, o);
    if (lane == 0) red[w] = yp;
    __syncthreads();
    if (tid == 0)
        g_yt[b] = red[0] + red[1] + red[2] + red[3]
                + x[b * 4096 + t * 64] * fcW[128] + fcb[0];
}

// ------------------------- final FC -------------------------
__global__ __launch_bounds__(128) void final_fc(const float* __restrict__ fcfW,
                                                const float* __restrict__ fcfb,
                                                float* __restrict__ out) {
    __shared__ float red[4];
    int b = blockIdx.x, tid = threadIdx.x;
    float p = g_dhA[b * HH + tid] * fcfW[tid] + g_ctx[b * HH + tid] * fcfW[128 + tid];
    #pragma unroll
    for (int o = 16; o; o >>= 1) p += __shfl_xor_sync(0xffffffffu, p, o);
    if ((tid & 31) == 0) red[tid >> 5] = p;
    __syncthreads();
    if (tid == 0) out[b] = red[0] + red[1] + red[2] + red[3] + fcfb[0];
}

// ------------------------- launch -------------------------
extern "C" void kernel_launch(void* const* d_in, const int* in_sizes, int n_in,
                              void* d_out, int out_size) {
    const float* x        = (const float*)d_in[0];
    const float* attnW    = (const float*)d_in[1];
    const float* attnB    = (const float*)d_in[2];
    const float* enc_Wih  = (const float*)d_in[3];
    const float* enc_Whh  = (const float*)d_in[4];
    const float* enc_bih  = (const float*)d_in[5];
    const float* enc_bhh  = (const float*)d_in[6];
    const float* dec_W1   = (const float*)d_in[7];
    const float* dec_b1   = (const float*)d_in[8];
    const float* dec_W2   = (const float*)d_in[9];
    // d_in[10] = dec_b2 (cancels in softmax)
    const float* dec_Wih  = (const float*)d_in[11];
    const float* dec_Whh  = (const float*)d_in[12];
    const float* dec_bih  = (const float*)d_in[13];
    const float* dec_bhh  = (const float*)d_in[14];
    const float* fc_W     = (const float*)d_in[15];
    const float* fc_b     = (const float*)d_in[16];
    const float* fcf_W    = (const float*)d_in[17];
    const float* fcf_b    = (const float*)d_in[18];
    float* out = (float*)d_out;

    zero_state<<<256, 256>>>();
    prep_weights<<<256, 256>>>(enc_Whh, dec_Whh, dec_Wih, dec_bih, dec_bhh);
    prep_attn<<<BB, 64>>>(x, attnW, attnB);
    gin_gemm<<<dim3(BB, 8), 256>>>(x, enc_Wih, enc_bih, enc_bhh);
    for (int t = 0; t < TT; t++)
        lstm_step<<<dim3(32, 8), 128>>>(t, 0);
    eproj_gemm<<<dim3(512, 2), 256>>>(dec_W1, dec_b1);
    for (int t = 0; t < TT; t++) {
        dec_proj<<<dim3(64, 2), 128>>>(dec_W1, t);
        dec_attn<<<BB, 256>>>(dec_W2, fc_W, fc_b, x, t);
        lstm_step<<<dim3(32, 8), 128>>>(t, 1);
    }
    final_fc<<<BB, 128>>>(fcf_W, fcf_b, out);
}